// round 11
// baseline (speedup 1.0000x reference)
#include <cuda_runtime.h>
#include <cuda_fp16.h>
#include <cstdint>

#define B_DIM 512
#define IN_F  1024
#define OUT_F 1024

// Device-global scratch (no allocation allowed in kernel_launch)
__device__ __half g_XQ[B_DIM * IN_F];   // fp16(round-nearest) of quantized x
__device__ __half g_WQ[OUT_F * IN_F];   // quantized weight (fp16-exact for this data)

// ---------------------------------------------------------------------------
// Helpers
// ---------------------------------------------------------------------------
__device__ __forceinline__ uint32_t smem_u32(const void* p) {
    uint32_t a;
    asm("{ .reg .u64 t; cvta.to.shared.u64 t, %1; cvt.u32.u64 %0, t; }" : "=r"(a) : "l"(p));
    return a;
}

#define MBARRIER_INIT(mbar, count) \
    asm volatile("mbarrier.init.shared.b64 [%0], %1;" :: "r"((uint32_t)(mbar)), "r"((uint32_t)(count)) : "memory")

#define MBARRIER_ARRIVE(mbar) \
    asm volatile("mbarrier.arrive.shared.b64 _, [%0];" :: "r"((uint32_t)(mbar)) : "memory")

// .noinc is load-bearing: without it the issue-time increment cancels the async
// arrive (net zero) and the barrier never flips -> deadlock (Round 10).
#define CPASYNC_MBAR_ARRIVE(mbar) \
    asm volatile("cp.async.mbarrier.arrive.noinc.shared.b64 [%0];" :: "r"((uint32_t)(mbar)) : "memory")

#define MBARRIER_WAIT_PARITY(mbar, parity) do {                                   \
    uint32_t _m = (uint32_t)(mbar);                                               \
    uint32_t _p = (uint32_t)(parity);                                             \
    uint32_t _done;                                                               \
    asm volatile("{\n\t.reg .pred p;\n\t"                                         \
        "mbarrier.try_wait.parity.acquire.cta.shared::cta.b64 p, [%1], %2;\n\t"   \
        "selp.b32 %0, 1, 0, p;\n\t}"                                              \
        : "=r"(_done) : "r"(_m), "r"(_p) : "memory");                             \
    if (!_done) {                                                                 \
        asm volatile("{\n\t.reg .pred P1;\n\t"                                    \
            "WAIT_LOOP_%=:\n\t"                                                   \
            "mbarrier.try_wait.parity.acquire.cta.shared::cta.b64 P1, [%0], %1, 0x989680;\n\t" \
            "@P1 bra.uni WAIT_DONE_%=;\n\t"                                       \
            "bra.uni WAIT_LOOP_%=;\n\t"                                           \
            "WAIT_DONE_%=:\n\t}"                                                  \
            :: "r"(_m), "r"(_p) : "memory");                                      \
    }                                                                             \
} while (0)

__device__ __forceinline__ float fixq_f(float v) {
    float q = rintf(v * 4096.0f);
    return fminf(fmaxf(q, -32768.0f), 32767.0f);
}

__device__ __forceinline__ float qout(float a) {
    float r = rintf(a * 2.44140625e-4f);            // acc * 2^-12
    r = fminf(fmaxf(r, -32768.0f), 32767.0f);
    return r * 2.44140625e-4f;                      // * 2^-12
}

__device__ __forceinline__ void cpa16(uint32_t s, const void* g) {
    asm volatile("cp.async.cg.shared.global [%0], [%1], 16;\n" :: "r"(s), "l"(g));
}
__device__ __forceinline__ void ldmx4(uint32_t r[4], uint32_t addr) {
    asm volatile("ldmatrix.sync.aligned.m8n8.x4.shared.b16 {%0,%1,%2,%3}, [%4];\n"
                 : "=r"(r[0]), "=r"(r[1]), "=r"(r[2]), "=r"(r[3]) : "r"(addr));
}
__device__ __forceinline__ void mma16816(float c[4], const uint32_t a[4], uint32_t b0, uint32_t b1) {
    asm volatile("mma.sync.aligned.m16n8k16.row.col.f32.f16.f16.f32 "
                 "{%0,%1,%2,%3}, {%4,%5,%6,%7}, {%8,%9}, {%0,%1,%2,%3};\n"
                 : "+f"(c[0]), "+f"(c[1]), "+f"(c[2]), "+f"(c[3])
                 : "r"(a[0]), "r"(a[1]), "r"(a[2]), "r"(a[3]), "r"(b0), "r"(b1));
}

// ---------------------------------------------------------------------------
// Fused quantization: blocks [0,256) handle x, [256,768) handle w.
// ---------------------------------------------------------------------------
__global__ __launch_bounds__(256) void quant_kernel(const float* __restrict__ x,
                                                    const float* __restrict__ w) {
    int b = blockIdx.x, t = threadIdx.x;
    if (b < 256) {
        int base = (b * 256 + t) * 8;
        float4 v0 = *reinterpret_cast<const float4*>(x + base);
        float4 v1 = *reinterpret_cast<const float4*>(x + base + 4);
        float f[8] = {v0.x, v0.y, v0.z, v0.w, v1.x, v1.y, v1.z, v1.w};
        __half h[8];
        #pragma unroll
        for (int i = 0; i < 8; i++) h[i] = __float2half_rn(fixq_f(f[i]));
        *reinterpret_cast<uint4*>(g_XQ + base) = *reinterpret_cast<uint4*>(h);
    } else {
        int base = ((b - 256) * 256 + t) * 8;
        float4 v0 = *reinterpret_cast<const float4*>(w + base);
        float4 v1 = *reinterpret_cast<const float4*>(w + base + 4);
        float f[8] = {v0.x, v0.y, v0.z, v0.w, v1.x, v1.y, v1.z, v1.w};
        __half h[8];
        #pragma unroll
        for (int i = 0; i < 8; i++) h[i] = __float2half_rn(fixq_f(f[i]));
        *reinterpret_cast<uint4*>(g_WQ + base) = *reinterpret_cast<uint4*>(h);
    }
}

// ---------------------------------------------------------------------------
// Warp-specialized GEMM: out[b,o] = qout(sum_k XQ[b,k] * WQ[o,k]) + bias[o]
// CTA tile 64x64, 384 threads: 8 consumer warps (0-7) + 4 producer warps (8-11).
// BK=64 (NIT=16), 6-stage mbarrier ring, NO __syncthreads in the mainloop.
// Consumers: 2x2 spatial grid of 32x32 warp tiles x 2-way split-K;
// each consumer warp waits full[s], does 8 LDSM + 16 MMA, arrives empty[s].
// Producers: wait empty[s], 8 cp.async each, cp.async.mbarrier.arrive.noinc -> full[s].
// Grid: (16, 8) = 128 CTAs.
// ---------------------------------------------------------------------------
#define BK        64
#define NIT       (IN_F / BK)        // 16
#define PITCH     72                 // halves per smem row (144B; conflict-free)
#define MAT_B     (64 * PITCH * 2)   // bytes per matrix tile (9216)
#define STAGE_B   (2 * MAT_B)        // XQ + WQ tiles (18432)
#define NSTG      6
#define SMEM_BYTES (NSTG * STAGE_B)  // 110592

__global__ __launch_bounds__(384) void mvm_gemm_kernel(const float* __restrict__ bias,
                                                       float* __restrict__ out) {
    extern __shared__ __align__(128) __half smem[];
    __shared__ __align__(8) uint64_t mbar[2 * NSTG];   // [full 0..5][empty 6..11]

    const int tid  = threadIdx.x;
    const int lane = tid & 31;
    const int warp = tid >> 5;        // 0..11
    const int bm0 = blockIdx.y * 64;
    const int bn0 = blockIdx.x * 64;

    const uint32_t smem_base = smem_u32(smem);
    const uint32_t mb = smem_u32(mbar);
    #define FULL(s)  (mb + (s) * 8)
    #define EMPTY(s) (mb + (NSTG + (s)) * 8)

    if (tid == 0) {
        #pragma unroll
        for (int s = 0; s < NSTG; ++s) {
            MBARRIER_INIT(FULL(s), 128);    // 128 producer threads arrive via cp.async.noinc
            MBARRIER_INIT(EMPTY(s), 256);   // 256 consumer threads arrive
        }
    }
    __syncthreads();

    if (warp >= 8) {
        // ---------------- Producer: 4 warps, 128 threads ----------------
        const int pt = tid - 256;            // 0..127
        const int r  = pt >> 1;              // row 0..63
        const int cb = (pt & 1) * 4;         // chunk base {0,4}
        const __half* gA = g_XQ + (size_t)(bm0 + r) * IN_F;
        const __half* gB = g_WQ + (size_t)(bn0 + r) * IN_F;

        int s = 0, ph = 1;                   // empty-phase starts at 1 (fresh pass)
        for (int p = 0; p < NIT; ++p) {
            MBARRIER_WAIT_PARITY(EMPTY(s), ph);
            const uint32_t so = smem_base + s * STAGE_B;
            const int k0 = p * BK;
            #pragma unroll
            for (int j = 0; j < 4; ++j) {
                const int col = (cb + j) * 8;                 // half offset
                const uint32_t d = so + (r * PITCH + col) * 2;
                cpa16(d,         gA + k0 + col);
                cpa16(d + MAT_B, gB + k0 + col);
            }
            CPASYNC_MBAR_ARRIVE(FULL(s));
            if (++s == NSTG) { s = 0; ph ^= 1; }
        }
        return;   // producers done
    }

    // ---------------- Consumers: 8 warps, 256 threads ----------------
    const int kg   = warp >> 2;       // k-group 0/1: handles ks = kg*2 + {0,1}
    const int wsub = warp & 3;
    const int wm = wsub >> 1, wn = wsub & 1;   // 2x2 grid of 32x32 warp tiles

    float acc[2][4][4];
    #pragma unroll
    for (int mi = 0; mi < 2; ++mi)
        #pragma unroll
        for (int nj = 0; nj < 4; ++nj)
            #pragma unroll
            for (int c = 0; c < 4; ++c) acc[mi][nj][c] = 0.0f;

    const uint32_t kgo    = kg * 64;  // 2 k16-steps = 64B
    const uint32_t laneA  = ((wm * 32 + (lane & 15)) * PITCH + (lane >> 4) * 8) * 2 + kgo;
    const uint32_t laneB0 = ((wn * 32 + ((lane >> 4) & 1) * 8 + (lane & 7)) * PITCH
                             + ((lane >> 3) & 1) * 8) * 2 + kgo;
    const uint32_t laneB1 = laneB0 + 16 * PITCH * 2;
    const uint32_t mStep  = 16 * PITCH * 2;

    int s = 0, ph = 0;
    for (int it = 0; it < NIT; ++it) {
        MBARRIER_WAIT_PARITY(FULL(s), ph);
        const uint32_t so   = smem_base + s * STAGE_B;
        const uint32_t aad  = so + laneA;
        const uint32_t bad0 = so + MAT_B + laneB0;
        const uint32_t bad1 = so + MAT_B + laneB1;

        uint32_t aa[2][2][4], bb[2][2][4];   // [ksj][mi or half][4]
        #pragma unroll
        for (int j = 0; j < 2; ++j) {
            const uint32_t ko = j * 32;      // 16 halves per ks
            ldmx4(aa[j][0], aad + ko);
            ldmx4(aa[j][1], aad + mStep + ko);
            ldmx4(bb[j][0], bad0 + ko);
            ldmx4(bb[j][1], bad1 + ko);
        }
        #pragma unroll
        for (int j = 0; j < 2; ++j)
            #pragma unroll
            for (int mi = 0; mi < 2; ++mi)
                #pragma unroll
                for (int nj = 0; nj < 4; ++nj) {
                    const uint32_t blo = bb[j][nj >> 1][(nj & 1) * 2];
                    const uint32_t bhi = bb[j][nj >> 1][(nj & 1) * 2 + 1];
                    mma16816(acc[mi][nj], aa[j][mi], blo, bhi);
                }
        MBARRIER_ARRIVE(EMPTY(s));           // after LDSMs: stage data consumed
        if (++s == NSTG) { s = 0; ph ^= 1; }
    }

    // ---- 2-way cross-k-group reduction (consumers only; named barrier) ----
    float4* red = reinterpret_cast<float4*>(smem);   // stage 0 region, now free
    asm volatile("bar.sync 1, 256;" ::: "memory");
    if (kg == 1) {
        #pragma unroll
        for (int mi = 0; mi < 2; ++mi)
            #pragma unroll
            for (int nj = 0; nj < 4; ++nj) {
                float4 v;
                v.x = acc[mi][nj][0]; v.y = acc[mi][nj][1];
                v.z = acc[mi][nj][2]; v.w = acc[mi][nj][3];
                red[((wsub * 8) + mi * 4 + nj) * 32 + lane] = v;
            }
    }
    asm volatile("bar.sync 1, 256;" ::: "memory");
    if (kg == 0) {
        #pragma unroll
        for (int mi = 0; mi < 2; ++mi) {
            const int gr = bm0 + wm * 32 + mi * 16 + (lane >> 2);
            #pragma unroll
            for (int nj = 0; nj < 4; ++nj) {
                float4 o = red[((wsub * 8) + mi * 4 + nj) * 32 + lane];
                const int gc = bn0 + wn * 32 + nj * 8 + (lane & 3) * 2;
                const float b0 = __ldg(&bias[gc]);
                const float b1 = __ldg(&bias[gc + 1]);
                float2 v0, v1;
                v0.x = qout(acc[mi][nj][0] + o.x) + b0;
                v0.y = qout(acc[mi][nj][1] + o.y) + b1;
                v1.x = qout(acc[mi][nj][2] + o.z) + b0;
                v1.y = qout(acc[mi][nj][3] + o.w) + b1;
                *reinterpret_cast<float2*>(&out[(size_t)gr * OUT_F + gc]) = v0;
                *reinterpret_cast<float2*>(&out[(size_t)(gr + 8) * OUT_F + gc]) = v1;
            }
        }
    }
}

extern "C" void kernel_launch(void* const* d_in, const int* in_sizes, int n_in,
                              void* d_out, int out_size) {
    const float* x    = (const float*)d_in[0];   // [512,1024]
    const float* w    = (const float*)d_in[1];   // [1024,1024] (out_f, in_f)
    const float* bias = (const float*)d_in[2];   // [1024]
    float* out = (float*)d_out;                  // [512,1024] float32

    cudaFuncSetAttribute(mvm_gemm_kernel,
                         cudaFuncAttributeMaxDynamicSharedMemorySize, SMEM_BYTES);

    quant_kernel<<<768, 256>>>(x, w);
    dim3 grid(OUT_F / 64, B_DIM / 64);           // 16 x 8 = 128 CTAs
    mvm_gemm_kernel<<<grid, 384, SMEM_BYTES>>>(bias, out);
}

// round 12
// speedup vs baseline: 1.1766x; 1.1766x over previous
#include <cuda_runtime.h>
#include <cuda_fp16.h>
#include <cstdint>

#define B_DIM 512
#define IN_F  1024
#define OUT_F 1024

// Device-global scratch (no allocation allowed in kernel_launch)
__device__ __half g_XQ[B_DIM * IN_F];   // fp16(round-nearest) of quantized x
__device__ __half g_WQ[OUT_F * IN_F];   // quantized weight (fp16-exact for this data)

// ---------------------------------------------------------------------------
// Helpers
// ---------------------------------------------------------------------------
__device__ __forceinline__ float fixq_f(float v) {
    float q = rintf(v * 4096.0f);
    return fminf(fmaxf(q, -32768.0f), 32767.0f);
}

__device__ __forceinline__ float qout(float a) {
    float r = rintf(a * 2.44140625e-4f);            // acc * 2^-12
    r = fminf(fmaxf(r, -32768.0f), 32767.0f);
    return r * 2.44140625e-4f;                      // * 2^-12
}

__device__ __forceinline__ void cpa16(uint32_t s, const void* g) {
    asm volatile("cp.async.cg.shared.global [%0], [%1], 16;\n" :: "r"(s), "l"(g));
}
__device__ __forceinline__ void ldmx4(uint32_t r[4], uint32_t addr) {
    asm volatile("ldmatrix.sync.aligned.m8n8.x4.shared.b16 {%0,%1,%2,%3}, [%4];\n"
                 : "=r"(r[0]), "=r"(r[1]), "=r"(r[2]), "=r"(r[3]) : "r"(addr));
}
__device__ __forceinline__ void mma16816(float c[4], const uint32_t a[4], uint32_t b0, uint32_t b1) {
    asm volatile("mma.sync.aligned.m16n8k16.row.col.f32.f16.f16.f32 "
                 "{%0,%1,%2,%3}, {%4,%5,%6,%7}, {%8,%9}, {%0,%1,%2,%3};\n"
                 : "+f"(c[0]), "+f"(c[1]), "+f"(c[2]), "+f"(c[3])
                 : "r"(a[0]), "r"(a[1]), "r"(a[2]), "r"(a[3]), "r"(b0), "r"(b1));
}

// ---------------------------------------------------------------------------
// Fused quantization: blocks [0,256) handle x, [256,768) handle w.
// ---------------------------------------------------------------------------
__global__ __launch_bounds__(256) void quant_kernel(const float* __restrict__ x,
                                                    const float* __restrict__ w) {
    int b = blockIdx.x, t = threadIdx.x;
    if (b < 256) {
        int base = (b * 256 + t) * 8;
        float4 v0 = *reinterpret_cast<const float4*>(x + base);
        float4 v1 = *reinterpret_cast<const float4*>(x + base + 4);
        float f[8] = {v0.x, v0.y, v0.z, v0.w, v1.x, v1.y, v1.z, v1.w};
        __half h[8];
        #pragma unroll
        for (int i = 0; i < 8; i++) h[i] = __float2half_rn(fixq_f(f[i]));
        *reinterpret_cast<uint4*>(g_XQ + base) = *reinterpret_cast<uint4*>(h);
    } else {
        int base = ((b - 256) * 256 + t) * 8;
        float4 v0 = *reinterpret_cast<const float4*>(w + base);
        float4 v1 = *reinterpret_cast<const float4*>(w + base + 4);
        float f[8] = {v0.x, v0.y, v0.z, v0.w, v1.x, v1.y, v1.z, v1.w};
        __half h[8];
        #pragma unroll
        for (int i = 0; i < 8; i++) h[i] = __float2half_rn(fixq_f(f[i]));
        *reinterpret_cast<uint4*>(g_WQ + base) = *reinterpret_cast<uint4*>(h);
    }
}

// ---------------------------------------------------------------------------
// GEMM: out[b,o] = qout(sum_k XQ[b,k] * WQ[o,k]) + bias[o]
// CTA tile 64(M) x 32(N), 256 threads / 8 warps, 2 CTAs resident per SM.
// BK=64 (NIT=16), 4-stage cp.async pipeline (R7 structure).
// 2-way warp split-K: k-group kg (4 warps, 2x2 grid of 32x16 warp tiles)
// handles ks = kg*2 + {0,1} of the 4 k16-steps per stage.
// Grid: (32, 8) = 256 CTAs  ->  ~2 co-resident CTAs/SM, no idle SMs.
// ---------------------------------------------------------------------------
#define BK        64
#define NIT       (IN_F / BK)        // 16
#define PITCH     72                 // halves per smem row (144B; conflict-free)
#define A_BYTES   (64 * PITCH * 2)   // 9216
#define B_BYTES   (32 * PITCH * 2)   // 4608
#define STAGE_B   (A_BYTES + B_BYTES)  // 13824
#define NSTAGES   4
#define SMEM_BYTES (NSTAGES * STAGE_B)   // 55296 -> 2 CTAs/SM fit in 228KB

__global__ __launch_bounds__(256, 2) void mvm_gemm_kernel(const float* __restrict__ bias,
                                                          float* __restrict__ out) {
    extern __shared__ __align__(128) __half smem[];

    const int tid  = threadIdx.x;
    const int lane = tid & 31;
    const int warp = tid >> 5;        // 0..7
    const int kg   = warp >> 2;       // k-group 0/1
    const int wsub = warp & 3;
    const int wm = wsub >> 1, wn = wsub & 1;   // 2x2 grid of 32x16 warp tiles
    const int bm0 = blockIdx.y * 64;
    const int bn0 = blockIdx.x * 32;

    float acc[2][2][4];
    #pragma unroll
    for (int mi = 0; mi < 2; ++mi)
        #pragma unroll
        for (int nj = 0; nj < 2; ++nj)
            #pragma unroll
            for (int c = 0; c < 4; ++c) acc[mi][nj][c] = 0.0f;

    const __half* gA = g_XQ + (size_t)bm0 * IN_F;
    const __half* gB = g_WQ + (size_t)bn0 * IN_F;

    // cp.async mapping:
    //   A: 64 rows x 8 chunks(16B) = 512 chunks -> 2/thread (4 threads/row)
    //   B: 32 rows x 8 chunks      = 256 chunks -> 1/thread (8 threads/row)
    const int ra  = tid >> 2;         // 0..63
    const int ca  = (tid & 3) * 2;    // chunk {0,2,4,6}
    const int rb  = tid >> 3;         // 0..31
    const int cb  = tid & 7;          // chunk 0..7
    const uint32_t smem_base = (uint32_t)__cvta_generic_to_shared(smem);

    auto prefetch = [&](int p) {
        const int s = p & (NSTAGES - 1);
        const uint32_t so = smem_base + s * STAGE_B;
        const int k0 = p * BK;
        const __half* a = gA + (size_t)ra * IN_F + k0;
        #pragma unroll
        for (int j = 0; j < 2; ++j) {
            const int col = (ca + j) * 8;
            cpa16(so + (ra * PITCH + col) * 2, a + col);
        }
        cpa16(so + A_BYTES + (rb * PITCH + cb * 8) * 2,
              gB + (size_t)rb * IN_F + k0 + cb * 8);
        asm volatile("cp.async.commit_group;\n" ::: "memory");
    };

    prefetch(0); prefetch(1); prefetch(2);

    // Per-lane fragment byte offsets (within a stage); k-group base = kg*2 ks = kg*64B
    const uint32_t kgo    = kg * 64;
    const uint32_t laneA  = ((wm * 32 + (lane & 15)) * PITCH + (lane >> 4) * 8) * 2 + kgo;
    const uint32_t laneB  = ((wn * 16 + ((lane >> 4) & 1) * 8 + (lane & 7)) * PITCH
                             + ((lane >> 3) & 1) * 8) * 2 + kgo;
    const uint32_t mStep  = 16 * PITCH * 2;   // +16 rows

    for (int it = 0; it < NIT; ++it) {
        if      (it < NIT - 2)  asm volatile("cp.async.wait_group 2;\n" ::: "memory");
        else if (it == NIT - 2) asm volatile("cp.async.wait_group 1;\n" ::: "memory");
        else                    asm volatile("cp.async.wait_group 0;\n" ::: "memory");
        __syncthreads();
        if (it + 3 < NIT) prefetch(it + 3);

        const int s = it & (NSTAGES - 1);
        const uint32_t so  = smem_base + s * STAGE_B;
        const uint32_t aad = so + laneA;
        const uint32_t bad = so + A_BYTES + laneB;

        // This k-group handles ks = kg*2 + {0,1}: load all fragments, then 8 MMAs
        uint32_t aa[2][2][4], bb[2][4];
        #pragma unroll
        for (int j = 0; j < 2; ++j) {
            const uint32_t ko = j * 32;       // 16 halves per ks
            ldmx4(aa[j][0], aad + ko);
            ldmx4(aa[j][1], aad + mStep + ko);
            ldmx4(bb[j],    bad + ko);
        }
        #pragma unroll
        for (int j = 0; j < 2; ++j)
            #pragma unroll
            for (int mi = 0; mi < 2; ++mi)
                #pragma unroll
                for (int nj = 0; nj < 2; ++nj)
                    mma16816(acc[mi][nj], aa[j][mi], bb[j][nj * 2], bb[j][nj * 2 + 1]);
    }

    // ---- 2-way cross-k-group reduction through smem ----
    float4* red = reinterpret_cast<float4*>(smem);
    __syncthreads();                  // all stages consumed; smem reusable
    if (kg == 1) {
        #pragma unroll
        for (int mi = 0; mi < 2; ++mi)
            #pragma unroll
            for (int nj = 0; nj < 2; ++nj) {
                float4 v;
                v.x = acc[mi][nj][0]; v.y = acc[mi][nj][1];
                v.z = acc[mi][nj][2]; v.w = acc[mi][nj][3];
                red[((wsub * 4) + mi * 2 + nj) * 32 + lane] = v;
            }
    }
    __syncthreads();
    if (kg == 0) {
        #pragma unroll
        for (int mi = 0; mi < 2; ++mi) {
            const int gr = bm0 + wm * 32 + mi * 16 + (lane >> 2);
            #pragma unroll
            for (int nj = 0; nj < 2; ++nj) {
                float4 o = red[((wsub * 4) + mi * 2 + nj) * 32 + lane];
                const int gc = bn0 + wn * 16 + nj * 8 + (lane & 3) * 2;
                const float b0 = __ldg(&bias[gc]);
                const float b1 = __ldg(&bias[gc + 1]);
                float2 v0, v1;
                v0.x = qout(acc[mi][nj][0] + o.x) + b0;
                v0.y = qout(acc[mi][nj][1] + o.y) + b1;
                v1.x = qout(acc[mi][nj][2] + o.z) + b0;
                v1.y = qout(acc[mi][nj][3] + o.w) + b1;
                *reinterpret_cast<float2*>(&out[(size_t)gr * OUT_F + gc]) = v0;
                *reinterpret_cast<float2*>(&out[(size_t)(gr + 8) * OUT_F + gc]) = v1;
            }
        }
    }
}

extern "C" void kernel_launch(void* const* d_in, const int* in_sizes, int n_in,
                              void* d_out, int out_size) {
    const float* x    = (const float*)d_in[0];   // [512,1024]
    const float* w    = (const float*)d_in[1];   // [1024,1024] (out_f, in_f)
    const float* bias = (const float*)d_in[2];   // [1024]
    float* out = (float*)d_out;                  // [512,1024] float32

    cudaFuncSetAttribute(mvm_gemm_kernel,
                         cudaFuncAttributeMaxDynamicSharedMemorySize, SMEM_BYTES);

    quant_kernel<<<768, 256>>>(x, w);
    dim3 grid(OUT_F / 32, B_DIM / 64);           // 32 x 8 = 256 CTAs
    mvm_gemm_kernel<<<grid, 256, SMEM_BYTES>>>(bias, out);
}